// round 12
// baseline (speedup 1.0000x reference)
#include <cuda_runtime.h>
#include <math.h>

#define NN 100000
#define EE 1600000
#define AA 500000
#define SS 50000
#define FW 64
#define NB_N 98     // ceil(NN/1024)
#define NB_S 49     // ceil(SS/1024)

typedef unsigned long long u64;

// ---------------- scratch (device globals: no allocations allowed) ------------
__device__ float h1_buf[NN * FW];       // post-elu hidden layers
__device__ float h2_buf[NN * FW];
__device__ float hagg_buf[NN * FW];     // segment-sum of current h (or x)
__device__ float zroot_buf[NN * FW];    // h @ w_root partial
__device__ float z3_buf[NN * FW];       // final pre-activation
__device__ int deg_buf[NN];
__device__ int row_start_buf[NN + 1];
__device__ int cursor_buf[NN];
__device__ int csr_src_buf[EE];
__device__ int seg_deg_buf[SS];
__device__ int seg_row_start[SS + 1];
__device__ int seg_cursor[SS];
__device__ int seg_val_buf[AA];
__device__ int blk_sums_buf[128];
__device__ int blk_sums2_buf[128];

__device__ __forceinline__ float elu_f(float x) { return x > 0.f ? x : expm1f(x); }

__device__ __forceinline__ u64 pk2(float lo, float hi) {
    u64 r;
    asm("mov.b64 %0, {%1,%2};" : "=l"(r) : "f"(lo), "f"(hi));
    return r;
}
__device__ __forceinline__ void fma2(u64& d, u64 a, u64 b) {
    asm("fma.rn.f32x2 %0, %1, %2, %0;" : "+l"(d) : "l"(a), "l"(b));
}

// ---------------- init ----------------------------------------------------------
__global__ void zero_init() {
    int i = blockIdx.x * 256 + threadIdx.x;
    if (i < NN) deg_buf[i] = 0;
    if (i < SS) seg_deg_buf[i] = 0;
}

// ---------------- generic CSR build ---------------------------------------------
__global__ void degree_count_g(const int* __restrict__ id, int* __restrict__ deg, int n) {
    int e = blockIdx.x * 256 + threadIdx.x;
    if (e < n) atomicAdd(&deg[id[e]], 1);
}

__global__ void scan_deg(const int* __restrict__ deg, int* __restrict__ rowst,
                         int* __restrict__ blks, int n) {
    __shared__ int sm[1024];
    int t = threadIdx.x, b = blockIdx.x;
    int i = b * 1024 + t;
    int v = (i < n) ? deg[i] : 0;
    sm[t] = v;
    __syncthreads();
    for (int off = 1; off < 1024; off <<= 1) {
        int x = (t >= off) ? sm[t - off] : 0;
        __syncthreads();
        sm[t] += x;
        __syncthreads();
    }
    if (i < n) rowst[i] = sm[t] - v;
    if (t == 1023) blks[b] = sm[t];
}

__global__ void scan_fin(int* __restrict__ rowst, int* __restrict__ cursor,
                         const int* __restrict__ blks, int n, int total, int nb) {
    __shared__ int sm[128];
    int t = threadIdx.x, b = blockIdx.x;
    if (t < 128) sm[t] = (t < b && t < nb) ? blks[t] : 0;
    __syncthreads();
    for (int o = 64; o > 0; o >>= 1) {
        if (t < o) sm[t] += sm[t + o];
        __syncthreads();
    }
    int off = sm[0];
    int i = b * 1024 + t;
    if (i < n) {
        int rs = rowst[i] + off;
        rowst[i] = rs;
        cursor[i] = rs;
    }
    if (i == 0) rowst[n] = total;
}

__global__ void csr_fill_g(const int* __restrict__ val, const int* __restrict__ dstid,
                           int* __restrict__ cursor, int* __restrict__ out, int n) {
    int e = blockIdx.x * 256 + threadIdx.x;
    if (e < n) {
        int d = dstid[e];
        int p = atomicAdd(&cursor[d], 1);
        out[p] = val[e];
    }
}

// ---------------- N=64 GEMM: out = [elu](zroot? + A@W + bias?) ------------------
// 256 threads, 32 rows/block, warp owns 4 rows, lane owns 2 cols (fma2 acc).
// insel: 0=x_in, 1=h1, 2=h2, 3=hagg.  outsel: 0=zroot, 1=h1, 2=h2, 3=z3.
// relmode: init acc with zroot+bias.  do_elu: activation at store.
__global__ void __launch_bounds__(256) gemm_n64(
    const float* __restrict__ x_in,
    const float* __restrict__ W,      // [k][c] row-major 64x64
    const float* __restrict__ bias,
    int insel, int outsel, int relmode, int do_elu)
{
    const float* A = (insel == 0) ? x_in
                   : (insel == 1) ? h1_buf
                   : (insel == 2) ? h2_buf : hagg_buf;
    float* out = (outsel == 0) ? zroot_buf
               : (outsel == 1) ? h1_buf
               : (outsel == 2) ? h2_buf : z3_buf;

    __shared__ float sw[64 * 64];
    __shared__ float sh[32 * 64];

    int tid = threadIdx.x;
    for (int i = tid; i < 4096; i += 256) sw[i] = W[i];
    int rowBase = blockIdx.x * 32;
    for (int i = tid; i < 2048; i += 256) sh[i] = A[(size_t)rowBase * 64 + i];
    __syncthreads();

    int warp = tid >> 5, lane = tid & 31;
    int r0 = warp * 4;

    u64 acc[4];
    if (relmode) {
        float2 b2 = *(const float2*)(bias + lane * 2);
#pragma unroll
        for (int r = 0; r < 4; r++) {
            float2 z2 = *(const float2*)(zroot_buf + (size_t)(rowBase + r0 + r) * 64 + lane * 2);
            acc[r] = pk2(z2.x + b2.x, z2.y + b2.y);
        }
    } else {
#pragma unroll
        for (int r = 0; r < 4; r++) acc[r] = 0ull;
    }

    const float* swp = sw + lane * 2;

#pragma unroll
    for (int k0 = 0; k0 < 64; k0 += 4) {
        float4 a4[4];
#pragma unroll
        for (int r = 0; r < 4; r++)
            a4[r] = *(const float4*)(sh + (r0 + r) * 64 + k0);   // broadcast
#pragma unroll
        for (int kk = 0; kk < 4; kk++) {
            u64 w2 = *(const u64*)(swp + ((k0 + kk) << 6));      // 256B/warp
#pragma unroll
            for (int r = 0; r < 4; r++) {
                float a = (kk == 0) ? a4[r].x : (kk == 1) ? a4[r].y
                        : (kk == 2) ? a4[r].z : a4[r].w;
                fma2(acc[r], pk2(a, a), w2);
            }
        }
    }

#pragma unroll
    for (int r = 0; r < 4; r++) {
        float2 o = *(float2*)&acc[r];
        if (do_elu) { o.x = elu_f(o.x); o.y = elu_f(o.y); }
        *(float2*)(out + (size_t)(rowBase + r0 + r) * 64 + lane * 2) = o;
    }
}

// ---------------- aggregation: hagg[i] = sum_{j in in(i)} h[j] ------------------
// exact R6 memory pattern; plain store (no read-modify-write).
__global__ void __launch_bounds__(256) agg_sum(const float* __restrict__ x_in, int insel) {
    const float* h = (insel == 0) ? x_in : (insel == 1) ? h1_buf : h2_buf;
    int node = (blockIdx.x * 256 + threadIdx.x) >> 5;  // NN/8 blocks
    int lane = threadIdx.x & 31;
    int half = lane >> 4, c4 = lane & 15;
    int s = row_start_buf[node], e = row_start_buf[node + 1];
    float4 acc = make_float4(0.f, 0.f, 0.f, 0.f);
    const float* gb = h + c4 * 4;

    int i = s + half;
    for (; i + 6 < e; i += 8) {         // 4 edges per half, 8 per warp
        int i0 = __ldg(&csr_src_buf[i]);
        int i1 = __ldg(&csr_src_buf[i + 2]);
        int i2 = __ldg(&csr_src_buf[i + 4]);
        int i3 = __ldg(&csr_src_buf[i + 6]);
        float4 v0 = *(const float4*)(gb + (size_t)i0 * FW);
        float4 v1 = *(const float4*)(gb + (size_t)i1 * FW);
        float4 v2 = *(const float4*)(gb + (size_t)i2 * FW);
        float4 v3 = *(const float4*)(gb + (size_t)i3 * FW);
        acc.x += (v0.x + v1.x) + (v2.x + v3.x);
        acc.y += (v0.y + v1.y) + (v2.y + v3.y);
        acc.z += (v0.z + v1.z) + (v2.z + v3.z);
        acc.w += (v0.w + v1.w) + (v2.w + v3.w);
    }
    for (; i < e; i += 2) {
        int srcn = __ldg(&csr_src_buf[i]);
        float4 v = *(const float4*)(gb + (size_t)srcn * FW);
        acc.x += v.x; acc.y += v.y; acc.z += v.z; acc.w += v.w;
    }

    acc.x += __shfl_xor_sync(0xffffffffu, acc.x, 16);
    acc.y += __shfl_xor_sync(0xffffffffu, acc.y, 16);
    acc.z += __shfl_xor_sync(0xffffffffu, acc.z, 16);
    acc.w += __shfl_xor_sync(0xffffffffu, acc.w, 16);
    if (lane < 16)
        *(float4*)(hagg_buf + (size_t)node * FW + c4 * 4) = acc;
}

// ---------------- fused pool + MLP head + log_softmax (exact R6, reads z3) -----
__global__ void __launch_bounds__(256) mlp_head(
    const float* __restrict__ fc1w, const float* __restrict__ fc1b,
    const float* __restrict__ fc2w, const float* __restrict__ fc2b,
    const float* __restrict__ fc3w, const float* __restrict__ fc3b,
    float* __restrict__ out)
{
    __shared__ u64 w1p[64 * 32];
    __shared__ u64 w2p[32 * 32];
    __shared__ float w3[64];
    __shared__ float b1[64], b2[32];
    __shared__ float sp[8][64];
    __shared__ float sh1[8][64];
    __shared__ float sh2[8][32];

    int tid = threadIdx.x;
    for (int i = tid; i < 2048; i += 256) {
        int k = i >> 5, l = i & 31;
        w1p[i] = pk2(fc1w[k * 64 + l], fc1w[k * 64 + l + 32]);
    }
    for (int i = tid; i < 1024; i += 256) {
        int k2 = i >> 5, l = i & 31;
        w2p[i] = pk2(fc2w[(2 * k2) * 32 + l], fc2w[(2 * k2 + 1) * 32 + l]);
    }
    if (tid < 64) w3[tid] = fc3w[tid];
    if (tid < 64) b1[tid] = fc1b[tid];
    if (tid < 32) b2[tid] = fc2b[tid];
    __syncthreads();

    int warp = tid >> 5, lane = tid & 31;
    int row = blockIdx.x * 8 + warp;

    int s = seg_row_start[row], e = seg_row_start[row + 1];
    float2 acc = make_float2(0.f, 0.f);
    const float* zb = z3_buf + lane * 2;
    int i = s;
    for (; i + 3 < e; i += 4) {
        int n0 = __ldg(&seg_val_buf[i]);
        int n1 = __ldg(&seg_val_buf[i + 1]);
        int n2 = __ldg(&seg_val_buf[i + 2]);
        int n3 = __ldg(&seg_val_buf[i + 3]);
        float2 v0 = *(const float2*)(zb + (size_t)n0 * FW);
        float2 v1 = *(const float2*)(zb + (size_t)n1 * FW);
        float2 v2 = *(const float2*)(zb + (size_t)n2 * FW);
        float2 v3 = *(const float2*)(zb + (size_t)n3 * FW);
        acc.x += elu_f(v0.x) + elu_f(v1.x) + elu_f(v2.x) + elu_f(v3.x);
        acc.y += elu_f(v0.y) + elu_f(v1.y) + elu_f(v2.y) + elu_f(v3.y);
    }
    for (; i < e; i++) {
        int n0 = __ldg(&seg_val_buf[i]);
        float2 v0 = *(const float2*)(zb + (size_t)n0 * FW);
        acc.x += elu_f(v0.x);
        acc.y += elu_f(v0.y);
    }
    sp[warp][lane * 2] = acc.x;
    sp[warp][lane * 2 + 1] = acc.y;
    __syncwarp();

    u64 acc12 = pk2(b1[lane], b1[lane + 32]);
#pragma unroll
    for (int k = 0; k < 64; k++) {
        float pk = sp[warp][k];
        fma2(acc12, pk2(pk, pk), w1p[k * 32 + lane]);
    }
    {
        float2 a12 = *(float2*)&acc12;
        sh1[warp][lane] = elu_f(a12.x);
        sh1[warp][lane + 32] = elu_f(a12.y);
    }
    __syncwarp();

    u64 acc2 = 0ull;
#pragma unroll
    for (int k2 = 0; k2 < 32; k2++) {
        u64 hpair = *(const u64*)(&sh1[warp][2 * k2]);
        fma2(acc2, hpair, w2p[k2 * 32 + lane]);
    }
    float a;
    {
        float2 a2f = *(float2*)&acc2;
        a = elu_f(a2f.x + a2f.y + b2[lane]);
    }
    sh2[warp][lane] = a;
    __syncwarp();

    float hv = sh2[warp][lane];
    float o0 = hv * w3[lane * 2];
    float o1 = hv * w3[lane * 2 + 1];
#pragma unroll
    for (int off = 16; off > 0; off >>= 1) {
        o0 += __shfl_down_sync(0xffffffffu, o0, off);
        o1 += __shfl_down_sync(0xffffffffu, o1, off);
    }
    if (lane == 0) {
        float l0 = o0 + fc3b[0];
        float l1 = o1 + fc3b[1];
        float m = fmaxf(l0, l1);
        float lse = m + logf(expf(l0 - m) + expf(l1 - m));
        out[row * 2]     = l0 - lse;
        out[row * 2 + 1] = l1 - lse;
    }
}

// ---------------- launch ---------------------------------------------------------
extern "C" void kernel_launch(void* const* d_in, const int* in_sizes, int n_in,
                              void* d_out, int out_size) {
    (void)in_sizes; (void)n_in; (void)out_size;
    const float* x       = (const float*)d_in[0];
    const int*   esrc    = (const int*)d_in[1];
    const int*   edst    = (const int*)d_in[2];
    const int*   gidx    = (const int*)d_in[3];
    const int*   sidx    = (const int*)d_in[4];
    const float* w_root0 = (const float*)d_in[5];
    const float* w_rel0  = (const float*)d_in[6];
    const float* b0      = (const float*)d_in[7];
    const float* w_rooth = (const float*)d_in[8];
    const float* w_relh  = (const float*)d_in[9];
    const float* b_h     = (const float*)d_in[10];
    const float* fc1w    = (const float*)d_in[11];
    const float* fc1b    = (const float*)d_in[12];
    const float* fc2w    = (const float*)d_in[13];
    const float* fc2b    = (const float*)d_in[14];
    const float* fc3w    = (const float*)d_in[15];
    const float* fc3b    = (const float*)d_in[16];
    float* out = (float*)d_out;

    int* dev_deg;   cudaGetSymbolAddress((void**)&dev_deg, deg_buf);
    int* dev_rs;    cudaGetSymbolAddress((void**)&dev_rs, row_start_buf);
    int* dev_cur;   cudaGetSymbolAddress((void**)&dev_cur, cursor_buf);
    int* dev_csr;   cudaGetSymbolAddress((void**)&dev_csr, csr_src_buf);
    int* dev_sdeg;  cudaGetSymbolAddress((void**)&dev_sdeg, seg_deg_buf);
    int* dev_srs;   cudaGetSymbolAddress((void**)&dev_srs, seg_row_start);
    int* dev_scur;  cudaGetSymbolAddress((void**)&dev_scur, seg_cursor);
    int* dev_sval;  cudaGetSymbolAddress((void**)&dev_sval, seg_val_buf);
    int* dev_bs;    cudaGetSymbolAddress((void**)&dev_bs, blk_sums_buf);
    int* dev_bs2;   cudaGetSymbolAddress((void**)&dev_bs2, blk_sums2_buf);

    static cudaStream_t s2 = nullptr;
    static cudaEvent_t evFork = nullptr, evZero = nullptr, evRoot0 = nullptr,
                       evSeg = nullptr, evH1 = nullptr, evH2 = nullptr,
                       evRoot1 = nullptr, evRoot2 = nullptr;
    if (s2 == nullptr) {
        cudaStreamCreateWithFlags(&s2, cudaStreamNonBlocking);
        cudaEventCreateWithFlags(&evFork, cudaEventDisableTiming);
        cudaEventCreateWithFlags(&evZero, cudaEventDisableTiming);
        cudaEventCreateWithFlags(&evRoot0, cudaEventDisableTiming);
        cudaEventCreateWithFlags(&evSeg, cudaEventDisableTiming);
        cudaEventCreateWithFlags(&evH1, cudaEventDisableTiming);
        cudaEventCreateWithFlags(&evH2, cudaEventDisableTiming);
        cudaEventCreateWithFlags(&evRoot1, cudaEventDisableTiming);
        cudaEventCreateWithFlags(&evRoot2, cudaEventDisableTiming);
    }

    cudaEventRecord(evFork, 0);
    cudaStreamWaitEvent(s2, evFork, 0);

    // main: zero + edge CSR
    zero_init<<<(NN + 255) / 256, 256>>>();                              // 0
    cudaEventRecord(evZero, 0);
    degree_count_g<<<EE / 256, 256>>>(edst, dev_deg, EE);                // 1
    scan_deg<<<NB_N, 1024>>>(dev_deg, dev_rs, dev_bs, NN);               // 2

    // s2: root0 = x @ w_root0 (needs only x + weights), then segment CSR
    gemm_n64<<<NN / 32, 256, 0, s2>>>(x, w_root0, b0, 0, 0, 0, 0);       // 3 (profiled)
    cudaEventRecord(evRoot0, s2);
    cudaStreamWaitEvent(s2, evZero, 0);
    degree_count_g<<<(AA + 255) / 256, 256, 0, s2>>>(sidx, dev_sdeg, AA);
    scan_deg<<<NB_S, 1024, 0, s2>>>(dev_sdeg, dev_srs, dev_bs2, SS);
    scan_fin<<<NB_S, 1024, 0, s2>>>(dev_srs, dev_scur, dev_bs2, SS, AA, NB_S);
    csr_fill_g<<<(AA + 255) / 256, 256, 0, s2>>>(gidx, sidx, dev_scur, dev_sval, AA);
    cudaEventRecord(evSeg, s2);

    // main: finish edge CSR
    scan_fin<<<NB_N, 1024>>>(dev_rs, dev_cur, dev_bs, NN, EE, NB_N);
    csr_fill_g<<<EE / 256, 256>>>(esrc, edst, dev_cur, dev_csr, EE);

    // ---- layer 0: hagg = Agg(x);  h1 = elu(zroot + hagg@w_rel0 + b0) ----
    agg_sum<<<NN / 8, 256>>>(x, 0);
    cudaStreamWaitEvent(0, evRoot0, 0);
    gemm_n64<<<NN / 32, 256>>>(x, w_rel0, b0, 3, 1, 1, 1);
    cudaEventRecord(evH1, 0);

    // ---- layer 1: root1 (s2) ∥ agg1 (main); then rel1 ----
    cudaStreamWaitEvent(s2, evH1, 0);
    gemm_n64<<<NN / 32, 256, 0, s2>>>(x, w_rooth, b_h, 1, 0, 0, 0);
    cudaEventRecord(evRoot1, s2);
    agg_sum<<<NN / 8, 256>>>(x, 1);
    cudaStreamWaitEvent(0, evRoot1, 0);
    gemm_n64<<<NN / 32, 256>>>(x, w_relh, b_h, 3, 2, 1, 1);
    cudaEventRecord(evH2, 0);

    // ---- layer 2: root2 (s2) ∥ agg2 (main); then rel2 (no elu) ----
    cudaStreamWaitEvent(s2, evH2, 0);
    gemm_n64<<<NN / 32, 256, 0, s2>>>(x, w_rooth + 4096, b_h + 64, 2, 0, 0, 0);
    cudaEventRecord(evRoot2, s2);
    agg_sum<<<NN / 8, 256>>>(x, 2);
    cudaStreamWaitEvent(0, evRoot2, 0);
    gemm_n64<<<NN / 32, 256>>>(x, w_relh + 4096, b_h + 64, 3, 3, 1, 0);

    // fused pool + head (needs z3 + segment CSR)
    cudaStreamWaitEvent(0, evSeg, 0);
    mlp_head<<<SS / 8, 256>>>(fc1w, fc1b, fc2w, fc2b, fc3w, fc3b, out);
}

// round 13
// speedup vs baseline: 1.1231x; 1.1231x over previous
#include <cuda_runtime.h>
#include <math.h>

#define NN 100000
#define EE 1600000
#define AA 500000
#define SS 50000
#define FW 64
#define NB_N 98     // ceil(NN/1024)
#define NB_S 49     // ceil(SS/1024)

typedef unsigned long long u64;

// ---------------- scratch (device globals: no allocations allowed) ------------
__device__ float g_buf[NN * FW];        // h @ w_rel per node
__device__ float zA_buf[NN * FW];       // pre-activation buffers (ping-pong)
__device__ float zB_buf[NN * FW];
__device__ int deg_buf[NN];
__device__ int row_start_buf[NN + 1];
__device__ int cursor_buf[NN];
__device__ int csr_src_buf[EE];
__device__ int seg_deg_buf[SS];
__device__ int seg_row_start[SS + 1];
__device__ int seg_cursor[SS];
__device__ int seg_val_buf[AA];
__device__ int blk_sums_buf[128];
__device__ int blk_sums2_buf[128];      // separate scratch: seg scan runs on s2

__device__ __forceinline__ float elu_f(float x) { return x > 0.f ? x : expm1f(x); }

__device__ __forceinline__ u64 pk2(float lo, float hi) {
    u64 r;
    asm("mov.b64 %0, {%1,%2};" : "=l"(r) : "f"(lo), "f"(hi));
    return r;
}
__device__ __forceinline__ void fma2(u64& d, u64 a, u64 b) {
    asm("fma.rn.f32x2 %0, %1, %2, %0;" : "+l"(d) : "l"(a), "l"(b));
}

// ---------------- init: zero both degree arrays --------------------------------
__global__ void zero_init() {    // grid covers NN
    int i = blockIdx.x * 256 + threadIdx.x;
    if (i < NN) deg_buf[i] = 0;
    if (i < SS) seg_deg_buf[i] = 0;
}

// ---------------- generic CSR build (used for edge CSR and segment CSR) --------
__global__ void degree_count_g(const int* __restrict__ id, int* __restrict__ deg, int n) {
    int e = blockIdx.x * 256 + threadIdx.x;
    if (e < n) atomicAdd(&deg[id[e]], 1);
}

__global__ void scan_deg(const int* __restrict__ deg, int* __restrict__ rowst,
                         int* __restrict__ blks, int n) {
    __shared__ int sm[1024];
    int t = threadIdx.x, b = blockIdx.x;
    int i = b * 1024 + t;
    int v = (i < n) ? deg[i] : 0;
    sm[t] = v;
    __syncthreads();
    for (int off = 1; off < 1024; off <<= 1) {
        int x = (t >= off) ? sm[t - off] : 0;
        __syncthreads();
        sm[t] += x;
        __syncthreads();
    }
    if (i < n) rowst[i] = sm[t] - v;  // block-local exclusive
    if (t == 1023) blks[b] = sm[t];
}

// redundant per-block reduction of preceding block sums, fused with final scatter
__global__ void scan_fin(int* __restrict__ rowst, int* __restrict__ cursor,
                         const int* __restrict__ blks, int n, int total, int nb) {
    __shared__ int sm[128];
    int t = threadIdx.x, b = blockIdx.x;
    if (t < 128) sm[t] = (t < b && t < nb) ? blks[t] : 0;
    __syncthreads();
    for (int o = 64; o > 0; o >>= 1) {
        if (t < o) sm[t] += sm[t + o];
        __syncthreads();
    }
    int off = sm[0];
    int i = b * 1024 + t;
    if (i < n) {
        int rs = rowst[i] + off;
        rowst[i] = rs;
        cursor[i] = rs;
    }
    if (i == 0) rowst[n] = total;
}

__global__ void csr_fill_g(const int* __restrict__ val, const int* __restrict__ dstid,
                           int* __restrict__ cursor, int* __restrict__ out, int n) {
    int e = blockIdx.x * 256 + threadIdx.x;
    if (e < n) {
        int d = dstid[e];
        int p = atomicAdd(&cursor[d], 1);
        out[p] = val[e];
    }
}

// ---------------- fused dual GEMM: z = elu?(h)@wr + b,  g = elu?(h)@wl --------
// EXACT R6 body: 256 threads, 32 rows/block, warp owns 4 rows, lane owns 4 cols
// (lanes 0-15 -> z cols, 16-31 -> g cols). f32x2 packed FMA. 48 regs, 57% occ.
__global__ void __launch_bounds__(256) gemm_dual(
    const float* __restrict__ x_in,
    const float* __restrict__ wr, const float* __restrict__ wl,
    const float* __restrict__ bias,
    int insel, int outsel)
{
    const float* hin = (insel == 0) ? x_in : (insel == 1 ? zA_buf : zB_buf);
    float* z = (outsel == 1) ? zA_buf : zB_buf;
    const bool ap = (insel != 0);

    __shared__ float sw[64 * 128];   // combined [k][c]: c<64 -> wr, c>=64 -> wl
    __shared__ float sh[32 * 64];    // h tile (post-elu)

    int tid = threadIdx.x;
    for (int idx = tid; idx < 64 * 128; idx += 256) {
        int k = idx >> 7, c = idx & 127;
        sw[idx] = (c < 64) ? wr[k * 64 + c] : wl[k * 64 + (c - 64)];
    }
    int rowBase = blockIdx.x * 32;
    for (int idx = tid; idx < 32 * 64; idx += 256) {
        float v = hin[rowBase * 64 + idx];
        if (ap) v = elu_f(v);
        sh[idx] = v;
    }
    __syncthreads();

    int warp = tid >> 5, lane = tid & 31;
    int r0 = warp * 4;

    u64 acc[4][2];
    if (lane < 16) {
        float4 b4 = *(const float4*)(bias + lane * 4);
        u64 bl = pk2(b4.x, b4.y), bh = pk2(b4.z, b4.w);
#pragma unroll
        for (int r = 0; r < 4; r++) { acc[r][0] = bl; acc[r][1] = bh; }
    } else {
#pragma unroll
        for (int r = 0; r < 4; r++) { acc[r][0] = 0ull; acc[r][1] = 0ull; }
    }

    const float* swp = sw + (lane << 2);

#pragma unroll
    for (int k0 = 0; k0 < 64; k0 += 4) {
        float4 a4[4];
#pragma unroll
        for (int r = 0; r < 4; r++)
            a4[r] = *(const float4*)(sh + (r0 + r) * 64 + k0);
#pragma unroll
        for (int kk = 0; kk < 4; kk++) {
            ulonglong2 wp = *(const ulonglong2*)(swp + ((k0 + kk) << 7));
#pragma unroll
            for (int r = 0; r < 4; r++) {
                float a = (kk == 0) ? a4[r].x : (kk == 1) ? a4[r].y
                        : (kk == 2) ? a4[r].z : a4[r].w;
                u64 a2 = pk2(a, a);
                fma2(acc[r][0], a2, wp.x);
                fma2(acc[r][1], a2, wp.y);
            }
        }
    }

#pragma unroll
    for (int r = 0; r < 4; r++) {
        int row = rowBase + r0 + r;
        float2 p0 = *(float2*)&acc[r][0];
        float2 p1 = *(float2*)&acc[r][1];
        float4 o = make_float4(p0.x, p0.y, p1.x, p1.y);
        if (lane < 16)
            *(float4*)(z + row * 64 + lane * 4) = o;
        else
            *(float4*)(g_buf + row * 64 + (lane - 16) * 4) = o;
    }
}

// ---------------- aggregation: z[i] += sum_{j in in(i)} g[j] ------------------
// NEW LAYOUT: warp per node; one warp instruction = all 32 lanes x float2 =
// one COMPLETE 256B edge row. Halves regs per in-flight edge vs float4 halves
// -> 8 edges in flight at the same register budget as R6's 4. No shfl needed:
// lane owns cols 2l,2l+1 end-to-end.
__global__ void __launch_bounds__(256) aggregate(int outsel) {
    float* z = (outsel == 1) ? zA_buf : zB_buf;
    int node = (blockIdx.x * 256 + threadIdx.x) >> 5;  // NN/8 = 12500 blocks
    int lane = threadIdx.x & 31;
    int s = row_start_buf[node], e = row_start_buf[node + 1];
    float2 acc0 = make_float2(0.f, 0.f);
    float2 acc1 = make_float2(0.f, 0.f);
    const float* gb = g_buf + lane * 2;

    int i = s;
    for (; i + 7 < e; i += 8) {          // 8 full edges in flight
        int i0 = __ldg(&csr_src_buf[i]);
        int i1 = __ldg(&csr_src_buf[i + 1]);
        int i2 = __ldg(&csr_src_buf[i + 2]);
        int i3 = __ldg(&csr_src_buf[i + 3]);
        int i4 = __ldg(&csr_src_buf[i + 4]);
        int i5 = __ldg(&csr_src_buf[i + 5]);
        int i6 = __ldg(&csr_src_buf[i + 6]);
        int i7 = __ldg(&csr_src_buf[i + 7]);
        float2 v0 = *(const float2*)(gb + (size_t)i0 * FW);
        float2 v1 = *(const float2*)(gb + (size_t)i1 * FW);
        float2 v2 = *(const float2*)(gb + (size_t)i2 * FW);
        float2 v3 = *(const float2*)(gb + (size_t)i3 * FW);
        float2 v4 = *(const float2*)(gb + (size_t)i4 * FW);
        float2 v5 = *(const float2*)(gb + (size_t)i5 * FW);
        float2 v6 = *(const float2*)(gb + (size_t)i6 * FW);
        float2 v7 = *(const float2*)(gb + (size_t)i7 * FW);
        acc0.x += (v0.x + v1.x) + (v2.x + v3.x);
        acc0.y += (v0.y + v1.y) + (v2.y + v3.y);
        acc1.x += (v4.x + v5.x) + (v6.x + v7.x);
        acc1.y += (v4.y + v5.y) + (v6.y + v7.y);
    }
    for (; i + 1 < e; i += 2) {
        int i0 = __ldg(&csr_src_buf[i]);
        int i1 = __ldg(&csr_src_buf[i + 1]);
        float2 v0 = *(const float2*)(gb + (size_t)i0 * FW);
        float2 v1 = *(const float2*)(gb + (size_t)i1 * FW);
        acc0.x += v0.x + v1.x;
        acc0.y += v0.y + v1.y;
    }
    if (i < e) {
        int i0 = __ldg(&csr_src_buf[i]);
        float2 v0 = *(const float2*)(gb + (size_t)i0 * FW);
        acc0.x += v0.x;
        acc0.y += v0.y;
    }
    acc0.x += acc1.x;
    acc0.y += acc1.y;

    float2* zp = (float2*)(z + (size_t)node * FW + lane * 2);
    float2 o = *zp;
    o.x += acc0.x;
    o.y += acc0.y;
    *zp = o;
}

// ---------------- fused pool + MLP head + log_softmax (warp per set row) ------
__global__ void __launch_bounds__(256) mlp_head(
    const float* __restrict__ fc1w, const float* __restrict__ fc1b,
    const float* __restrict__ fc2w, const float* __restrict__ fc2b,
    const float* __restrict__ fc3w, const float* __restrict__ fc3b,
    float* __restrict__ out)
{
    __shared__ u64 w1p[64 * 32];     // [k][l] = {w1[k][l], w1[k][l+32]}
    __shared__ u64 w2p[32 * 32];     // [k2][l] = {w2[2k2][l], w2[2k2+1][l]}
    __shared__ float w3[64];
    __shared__ float b1[64], b2[32];
    __shared__ float sp[8][64];
    __shared__ float sh1[8][64];
    __shared__ float sh2[8][32];

    int tid = threadIdx.x;
    for (int i = tid; i < 2048; i += 256) {
        int k = i >> 5, l = i & 31;
        w1p[i] = pk2(fc1w[k * 64 + l], fc1w[k * 64 + l + 32]);
    }
    for (int i = tid; i < 1024; i += 256) {
        int k2 = i >> 5, l = i & 31;
        w2p[i] = pk2(fc2w[(2 * k2) * 32 + l], fc2w[(2 * k2 + 1) * 32 + l]);
    }
    if (tid < 64) w3[tid] = fc3w[tid];
    if (tid < 64) b1[tid] = fc1b[tid];
    if (tid < 32) b2[tid] = fc2b[tid];
    __syncthreads();

    int warp = tid >> 5, lane = tid & 31;
    int row = blockIdx.x * 8 + warp;   // SS/8 = 6250 blocks exact

    // inline segment pooling: lane owns 2 feature cols
    int s = seg_row_start[row], e = seg_row_start[row + 1];
    float2 acc = make_float2(0.f, 0.f);
    const float* zb = zA_buf + lane * 2;
    int i = s;
    for (; i + 3 < e; i += 4) {
        int n0 = __ldg(&seg_val_buf[i]);
        int n1 = __ldg(&seg_val_buf[i + 1]);
        int n2 = __ldg(&seg_val_buf[i + 2]);
        int n3 = __ldg(&seg_val_buf[i + 3]);
        float2 v0 = *(const float2*)(zb + (size_t)n0 * FW);
        float2 v1 = *(const float2*)(zb + (size_t)n1 * FW);
        float2 v2 = *(const float2*)(zb + (size_t)n2 * FW);
        float2 v3 = *(const float2*)(zb + (size_t)n3 * FW);
        acc.x += elu_f(v0.x) + elu_f(v1.x) + elu_f(v2.x) + elu_f(v3.x);
        acc.y += elu_f(v0.y) + elu_f(v1.y) + elu_f(v2.y) + elu_f(v3.y);
    }
    for (; i < e; i++) {
        int n0 = __ldg(&seg_val_buf[i]);
        float2 v0 = *(const float2*)(zb + (size_t)n0 * FW);
        acc.x += elu_f(v0.x);
        acc.y += elu_f(v0.y);
    }
    sp[warp][lane * 2] = acc.x;
    sp[warp][lane * 2 + 1] = acc.y;
    __syncwarp();

    // fc1 (64->64) + elu : packed over the two output halves
    u64 acc12 = pk2(b1[lane], b1[lane + 32]);
#pragma unroll
    for (int k = 0; k < 64; k++) {
        float pk = sp[warp][k];
        fma2(acc12, pk2(pk, pk), w1p[k * 32 + lane]);
    }
    {
        float2 a12 = *(float2*)&acc12;
        sh1[warp][lane] = elu_f(a12.x);
        sh1[warp][lane + 32] = elu_f(a12.y);
    }
    __syncwarp();

    // fc2 (64->32) + elu : packed over even/odd k
    u64 acc2 = 0ull;
#pragma unroll
    for (int k2 = 0; k2 < 32; k2++) {
        u64 hpair = *(const u64*)(&sh1[warp][2 * k2]);
        fma2(acc2, hpair, w2p[k2 * 32 + lane]);
    }
    float a;
    {
        float2 a2f = *(float2*)&acc2;
        a = elu_f(a2f.x + a2f.y + b2[lane]);
    }
    sh2[warp][lane] = a;
    __syncwarp();

    // fc3 (32->2): lane l contributes k=l, warp-reduce
    float hv = sh2[warp][lane];
    float o0 = hv * w3[lane * 2];
    float o1 = hv * w3[lane * 2 + 1];
#pragma unroll
    for (int off = 16; off > 0; off >>= 1) {
        o0 += __shfl_down_sync(0xffffffffu, o0, off);
        o1 += __shfl_down_sync(0xffffffffu, o1, off);
    }
    if (lane == 0) {
        float l0 = o0 + fc3b[0];
        float l1 = o1 + fc3b[1];
        float m = fmaxf(l0, l1);
        float lse = m + logf(expf(l0 - m) + expf(l1 - m));
        out[row * 2]     = l0 - lse;
        out[row * 2 + 1] = l1 - lse;
    }
}

// ---------------- launch -------------------------------------------------------
extern "C" void kernel_launch(void* const* d_in, const int* in_sizes, int n_in,
                              void* d_out, int out_size) {
    (void)in_sizes; (void)n_in; (void)out_size;
    const float* x       = (const float*)d_in[0];
    const int*   esrc    = (const int*)d_in[1];
    const int*   edst    = (const int*)d_in[2];
    const int*   gidx    = (const int*)d_in[3];
    const int*   sidx    = (const int*)d_in[4];
    const float* w_root0 = (const float*)d_in[5];
    const float* w_rel0  = (const float*)d_in[6];
    const float* b0      = (const float*)d_in[7];
    const float* w_rooth = (const float*)d_in[8];
    const float* w_relh  = (const float*)d_in[9];
    const float* b_h     = (const float*)d_in[10];
    const float* fc1w    = (const float*)d_in[11];
    const float* fc1b    = (const float*)d_in[12];
    const float* fc2w    = (const float*)d_in[13];
    const float* fc2b    = (const float*)d_in[14];
    const float* fc3w    = (const float*)d_in[15];
    const float* fc3b    = (const float*)d_in[16];
    float* out = (float*)d_out;

    int* dev_deg;   cudaGetSymbolAddress((void**)&dev_deg, deg_buf);
    int* dev_rs;    cudaGetSymbolAddress((void**)&dev_rs, row_start_buf);
    int* dev_cur;   cudaGetSymbolAddress((void**)&dev_cur, cursor_buf);
    int* dev_csr;   cudaGetSymbolAddress((void**)&dev_csr, csr_src_buf);
    int* dev_sdeg;  cudaGetSymbolAddress((void**)&dev_sdeg, seg_deg_buf);
    int* dev_srs;   cudaGetSymbolAddress((void**)&dev_srs, seg_row_start);
    int* dev_scur;  cudaGetSymbolAddress((void**)&dev_scur, seg_cursor);
    int* dev_sval;  cudaGetSymbolAddress((void**)&dev_sval, seg_val_buf);
    int* dev_bs;    cudaGetSymbolAddress((void**)&dev_bs, blk_sums_buf);
    int* dev_bs2;   cudaGetSymbolAddress((void**)&dev_bs2, blk_sums2_buf);

    // side stream + events (created once; no device allocations)
    static cudaStream_t s2 = nullptr;
    static cudaEvent_t evFork = nullptr, evZero = nullptr, evJoin = nullptr, evJoin2 = nullptr;
    if (s2 == nullptr) {
        cudaStreamCreateWithFlags(&s2, cudaStreamNonBlocking);
        cudaEventCreateWithFlags(&evFork, cudaEventDisableTiming);
        cudaEventCreateWithFlags(&evZero, cudaEventDisableTiming);
        cudaEventCreateWithFlags(&evJoin, cudaEventDisableTiming);
        cudaEventCreateWithFlags(&evJoin2, cudaEventDisableTiming);
    }

    cudaEventRecord(evFork, 0);
    cudaStreamWaitEvent(s2, evFork, 0);

    // main: zero counters + edge CSR
    zero_init<<<(NN + 255) / 256, 256>>>();                           // 0
    cudaEventRecord(evZero, 0);
    degree_count_g<<<EE / 256, 256>>>(edst, dev_deg, EE);             // 1
    scan_deg<<<NB_N, 1024>>>(dev_deg, dev_rs, dev_bs, NN);            // 2

    // s2: layer-0 GEMM (only needs x + weights), then segment CSR
    gemm_dual<<<NN / 32, 256, 0, s2>>>(x, w_root0, w_rel0, b0, 0, 1); // 3 (profiled)
    cudaEventRecord(evJoin, s2);
    cudaStreamWaitEvent(s2, evZero, 0);
    degree_count_g<<<(AA + 255) / 256, 256, 0, s2>>>(sidx, dev_sdeg, AA);
    scan_deg<<<NB_S, 1024, 0, s2>>>(dev_sdeg, dev_srs, dev_bs2, SS);
    scan_fin<<<NB_S, 1024, 0, s2>>>(dev_srs, dev_scur, dev_bs2, SS, AA, NB_S);
    csr_fill_g<<<(AA + 255) / 256, 256, 0, s2>>>(gidx, sidx, dev_scur, dev_sval, AA);
    cudaEventRecord(evJoin2, s2);

    // main: finish edge CSR
    scan_fin<<<NB_N, 1024>>>(dev_rs, dev_cur, dev_bs, NN, EE, NB_N);
    csr_fill_g<<<EE / 256, 256>>>(esrc, edst, dev_cur, dev_csr, EE);

    // join: aggregation needs both edge CSR and gemm0 outputs
    cudaStreamWaitEvent(0, evJoin, 0);
    aggregate<<<NN / 8, 256>>>(1);
    // layer 1: elu(zA) -> zB
    gemm_dual<<<NN / 32, 256>>>(x, w_rooth, w_relh, b_h, 1, 2);
    aggregate<<<NN / 8, 256>>>(2);
    // layer 2: elu(zB) -> zA
    gemm_dual<<<NN / 32, 256>>>(x, w_rooth + 4096, w_relh + 4096, b_h + 64, 2, 1);
    aggregate<<<NN / 8, 256>>>(1);

    // fused pool + head (needs segment CSR from s2)
    cudaStreamWaitEvent(0, evJoin2, 0);
    mlp_head<<<SS / 8, 256>>>(fc1w, fc1b, fc2w, fc2b, fc3w, fc3b, out);
}

// round 14
// speedup vs baseline: 1.2617x; 1.1234x over previous
#include <cuda_runtime.h>
#include <math.h>

#define NN 100000
#define EE 1600000
#define AA 500000
#define SS 50000
#define FW 64
#define NB_N 98     // ceil(NN/1024)
#define NB_S 49     // ceil(SS/1024)
#define NTILES 3125 // NN/32
#define PGRID 740   // 5 blocks/SM x 148 SMs (exact residency)

typedef unsigned long long u64;

// ---------------- scratch (device globals: no allocations allowed) ------------
__device__ float g_buf[NN * FW];        // h @ w_rel per node
__device__ float zA_buf[NN * FW];       // pre-activation buffers (ping-pong)
__device__ float zB_buf[NN * FW];
__device__ int deg_buf[NN];
__device__ int row_start_buf[NN + 1];
__device__ int cursor_buf[NN];
__device__ int csr_src_buf[EE];
__device__ int seg_deg_buf[SS];
__device__ int seg_row_start[SS + 1];
__device__ int seg_cursor[SS];
__device__ int seg_val_buf[AA];
__device__ int blk_sums_buf[128];
__device__ int blk_sums2_buf[128];      // separate scratch: seg scan runs on s2

__device__ __forceinline__ float elu_f(float x) { return x > 0.f ? x : expm1f(x); }

__device__ __forceinline__ u64 pk2(float lo, float hi) {
    u64 r;
    asm("mov.b64 %0, {%1,%2};" : "=l"(r) : "f"(lo), "f"(hi));
    return r;
}
__device__ __forceinline__ void fma2(u64& d, u64 a, u64 b) {
    asm("fma.rn.f32x2 %0, %1, %2, %0;" : "+l"(d) : "l"(a), "l"(b));
}

// ---------------- init: zero both degree arrays --------------------------------
__global__ void zero_init() {    // grid covers NN
    int i = blockIdx.x * 256 + threadIdx.x;
    if (i < NN) deg_buf[i] = 0;
    if (i < SS) seg_deg_buf[i] = 0;
}

// ---------------- generic CSR build (used for edge CSR and segment CSR) --------
__global__ void degree_count_g(const int* __restrict__ id, int* __restrict__ deg, int n) {
    int e = blockIdx.x * 256 + threadIdx.x;
    if (e < n) atomicAdd(&deg[id[e]], 1);
}

__global__ void scan_deg(const int* __restrict__ deg, int* __restrict__ rowst,
                         int* __restrict__ blks, int n) {
    __shared__ int sm[1024];
    int t = threadIdx.x, b = blockIdx.x;
    int i = b * 1024 + t;
    int v = (i < n) ? deg[i] : 0;
    sm[t] = v;
    __syncthreads();
    for (int off = 1; off < 1024; off <<= 1) {
        int x = (t >= off) ? sm[t - off] : 0;
        __syncthreads();
        sm[t] += x;
        __syncthreads();
    }
    if (i < n) rowst[i] = sm[t] - v;  // block-local exclusive
    if (t == 1023) blks[b] = sm[t];
}

// redundant per-block reduction of preceding block sums, fused with final scatter
__global__ void scan_fin(int* __restrict__ rowst, int* __restrict__ cursor,
                         const int* __restrict__ blks, int n, int total, int nb) {
    __shared__ int sm[128];
    int t = threadIdx.x, b = blockIdx.x;
    if (t < 128) sm[t] = (t < b && t < nb) ? blks[t] : 0;
    __syncthreads();
    for (int o = 64; o > 0; o >>= 1) {
        if (t < o) sm[t] += sm[t + o];
        __syncthreads();
    }
    int off = sm[0];
    int i = b * 1024 + t;
    if (i < n) {
        int rs = rowst[i] + off;
        rowst[i] = rs;
        cursor[i] = rs;
    }
    if (i == 0) rowst[n] = total;
}

__global__ void csr_fill_g(const int* __restrict__ val, const int* __restrict__ dstid,
                           int* __restrict__ cursor, int* __restrict__ out, int n) {
    int e = blockIdx.x * 256 + threadIdx.x;
    if (e < n) {
        int d = dstid[e];
        int p = atomicAdd(&cursor[d], 1);
        out[p] = val[e];
    }
}

// ---------------- fused dual GEMM: z = elu?(h)@wr + b,  g = elu?(h)@wl --------
// PERSISTENT version of the R6 kernel: grid = 740 (exact residency), each block
// loads the 32KB combined weight tile ONCE and loops over ~4-5 row-tiles.
// Inner tile: warp owns 4 rows, lane owns 4 cols (lanes 0-15 -> z, 16-31 -> g).
__global__ void __launch_bounds__(256) gemm_dual(
    const float* __restrict__ x_in,
    const float* __restrict__ wr, const float* __restrict__ wl,
    const float* __restrict__ bias,
    int insel, int outsel)
{
    const float* hin = (insel == 0) ? x_in : (insel == 1 ? zA_buf : zB_buf);
    float* z = (outsel == 1) ? zA_buf : zB_buf;
    const bool ap = (insel != 0);

    __shared__ float sw[64 * 128];   // combined [k][c]: c<64 -> wr, c>=64 -> wl
    __shared__ float sh[32 * 64];    // h tile (post-elu)

    int tid = threadIdx.x;
    // weights loaded ONCE per block (amortized over all tiles)
    for (int idx = tid; idx < 64 * 128; idx += 256) {
        int k = idx >> 7, c = idx & 127;
        sw[idx] = (c < 64) ? wr[k * 64 + c] : wl[k * 64 + (c - 64)];
    }

    int warp = tid >> 5, lane = tid & 31;
    int r0 = warp * 4;

    u64 bias0 = 0ull, bias1 = 0ull;
    if (lane < 16) {
        float4 b4 = *(const float4*)(bias + lane * 4);
        bias0 = pk2(b4.x, b4.y);
        bias1 = pk2(b4.z, b4.w);
    }

    const float* swp = sw + (lane << 2);

    for (int tile = blockIdx.x; tile < NTILES; tile += PGRID) {
        int rowBase = tile * 32;
        __syncthreads();                 // prior compute done before sh overwrite
        for (int idx = tid; idx < 32 * 64; idx += 256) {
            float v = hin[(size_t)rowBase * 64 + idx];
            if (ap) v = elu_f(v);
            sh[idx] = v;
        }
        __syncthreads();

        u64 acc[4][2];
#pragma unroll
        for (int r = 0; r < 4; r++) { acc[r][0] = bias0; acc[r][1] = bias1; }

#pragma unroll
        for (int k0 = 0; k0 < 64; k0 += 4) {
            float4 a4[4];
#pragma unroll
            for (int r = 0; r < 4; r++)
                a4[r] = *(const float4*)(sh + (r0 + r) * 64 + k0);
#pragma unroll
            for (int kk = 0; kk < 4; kk++) {
                ulonglong2 wp = *(const ulonglong2*)(swp + ((k0 + kk) << 7));
#pragma unroll
                for (int r = 0; r < 4; r++) {
                    float a = (kk == 0) ? a4[r].x : (kk == 1) ? a4[r].y
                            : (kk == 2) ? a4[r].z : a4[r].w;
                    u64 a2 = pk2(a, a);
                    fma2(acc[r][0], a2, wp.x);
                    fma2(acc[r][1], a2, wp.y);
                }
            }
        }

#pragma unroll
        for (int r = 0; r < 4; r++) {
            int row = rowBase + r0 + r;
            float2 p0 = *(float2*)&acc[r][0];
            float2 p1 = *(float2*)&acc[r][1];
            float4 o = make_float4(p0.x, p0.y, p1.x, p1.y);
            if (lane < 16)
                *(float4*)(z + (size_t)row * 64 + lane * 4) = o;
            else
                *(float4*)(g_buf + (size_t)row * 64 + (lane - 16) * 4) = o;
        }
    }
}

// ---------------- aggregation (EXACT R6): z[i] += sum_{j in in(i)} g[j] --------
// warp per node; 2 lane-halves x float4; 4 edges in flight per half.
__global__ void __launch_bounds__(256) aggregate(int outsel) {
    float* z = (outsel == 1) ? zA_buf : zB_buf;
    int node = (blockIdx.x * 256 + threadIdx.x) >> 5;  // NN/8 = 12500 blocks
    int lane = threadIdx.x & 31;
    int half = lane >> 4, c4 = lane & 15;
    int s = row_start_buf[node], e = row_start_buf[node + 1];
    float4 acc = make_float4(0.f, 0.f, 0.f, 0.f);
    const float* gb = g_buf + c4 * 4;

    int i = s + half;
    for (; i + 6 < e; i += 8) {         // 4 edges per half, 8 per warp
        int i0 = __ldg(&csr_src_buf[i]);
        int i1 = __ldg(&csr_src_buf[i + 2]);
        int i2 = __ldg(&csr_src_buf[i + 4]);
        int i3 = __ldg(&csr_src_buf[i + 6]);
        float4 v0 = *(const float4*)(gb + (size_t)i0 * FW);
        float4 v1 = *(const float4*)(gb + (size_t)i1 * FW);
        float4 v2 = *(const float4*)(gb + (size_t)i2 * FW);
        float4 v3 = *(const float4*)(gb + (size_t)i3 * FW);
        acc.x += (v0.x + v1.x) + (v2.x + v3.x);
        acc.y += (v0.y + v1.y) + (v2.y + v3.y);
        acc.z += (v0.z + v1.z) + (v2.z + v3.z);
        acc.w += (v0.w + v1.w) + (v2.w + v3.w);
    }
    for (; i < e; i += 2) {
        int srcn = __ldg(&csr_src_buf[i]);
        float4 v = *(const float4*)(gb + (size_t)srcn * FW);
        acc.x += v.x; acc.y += v.y; acc.z += v.z; acc.w += v.w;
    }

    acc.x += __shfl_xor_sync(0xffffffffu, acc.x, 16);
    acc.y += __shfl_xor_sync(0xffffffffu, acc.y, 16);
    acc.z += __shfl_xor_sync(0xffffffffu, acc.z, 16);
    acc.w += __shfl_xor_sync(0xffffffffu, acc.w, 16);
    if (lane < 16) {
        float4* zp = (float4*)(z + (size_t)node * FW + c4 * 4);
        float4 o = *zp;
        o.x += acc.x; o.y += acc.y; o.z += acc.z; o.w += acc.w;
        *zp = o;
    }
}

// ---------------- fused pool + MLP head + log_softmax (EXACT R6) ---------------
__global__ void __launch_bounds__(256) mlp_head(
    const float* __restrict__ fc1w, const float* __restrict__ fc1b,
    const float* __restrict__ fc2w, const float* __restrict__ fc2b,
    const float* __restrict__ fc3w, const float* __restrict__ fc3b,
    float* __restrict__ out)
{
    __shared__ u64 w1p[64 * 32];     // [k][l] = {w1[k][l], w1[k][l+32]}
    __shared__ u64 w2p[32 * 32];     // [k2][l] = {w2[2k2][l], w2[2k2+1][l]}
    __shared__ float w3[64];
    __shared__ float b1[64], b2[32];
    __shared__ float sp[8][64];
    __shared__ float sh1[8][64];
    __shared__ float sh2[8][32];

    int tid = threadIdx.x;
    for (int i = tid; i < 2048; i += 256) {
        int k = i >> 5, l = i & 31;
        w1p[i] = pk2(fc1w[k * 64 + l], fc1w[k * 64 + l + 32]);
    }
    for (int i = tid; i < 1024; i += 256) {
        int k2 = i >> 5, l = i & 31;
        w2p[i] = pk2(fc2w[(2 * k2) * 32 + l], fc2w[(2 * k2 + 1) * 32 + l]);
    }
    if (tid < 64) w3[tid] = fc3w[tid];
    if (tid < 64) b1[tid] = fc1b[tid];
    if (tid < 32) b2[tid] = fc2b[tid];
    __syncthreads();

    int warp = tid >> 5, lane = tid & 31;
    int row = blockIdx.x * 8 + warp;   // SS/8 = 6250 blocks exact

    // inline segment pooling: lane owns 2 feature cols
    int s = seg_row_start[row], e = seg_row_start[row + 1];
    float2 acc = make_float2(0.f, 0.f);
    const float* zb = zA_buf + lane * 2;
    int i = s;
    for (; i + 3 < e; i += 4) {
        int n0 = __ldg(&seg_val_buf[i]);
        int n1 = __ldg(&seg_val_buf[i + 1]);
        int n2 = __ldg(&seg_val_buf[i + 2]);
        int n3 = __ldg(&seg_val_buf[i + 3]);
        float2 v0 = *(const float2*)(zb + (size_t)n0 * FW);
        float2 v1 = *(const float2*)(zb + (size_t)n1 * FW);
        float2 v2 = *(const float2*)(zb + (size_t)n2 * FW);
        float2 v3 = *(const float2*)(zb + (size_t)n3 * FW);
        acc.x += elu_f(v0.x) + elu_f(v1.x) + elu_f(v2.x) + elu_f(v3.x);
        acc.y += elu_f(v0.y) + elu_f(v1.y) + elu_f(v2.y) + elu_f(v3.y);
    }
    for (; i < e; i++) {
        int n0 = __ldg(&seg_val_buf[i]);
        float2 v0 = *(const float2*)(zb + (size_t)n0 * FW);
        acc.x += elu_f(v0.x);
        acc.y += elu_f(v0.y);
    }
    sp[warp][lane * 2] = acc.x;
    sp[warp][lane * 2 + 1] = acc.y;
    __syncwarp();

    // fc1 (64->64) + elu : packed over the two output halves
    u64 acc12 = pk2(b1[lane], b1[lane + 32]);
#pragma unroll
    for (int k = 0; k < 64; k++) {
        float pk = sp[warp][k];
        fma2(acc12, pk2(pk, pk), w1p[k * 32 + lane]);
    }
    {
        float2 a12 = *(float2*)&acc12;
        sh1[warp][lane] = elu_f(a12.x);
        sh1[warp][lane + 32] = elu_f(a12.y);
    }
    __syncwarp();

    // fc2 (64->32) + elu : packed over even/odd k
    u64 acc2 = 0ull;
#pragma unroll
    for (int k2 = 0; k2 < 32; k2++) {
        u64 hpair = *(const u64*)(&sh1[warp][2 * k2]);
        fma2(acc2, hpair, w2p[k2 * 32 + lane]);
    }
    float a;
    {
        float2 a2f = *(float2*)&acc2;
        a = elu_f(a2f.x + a2f.y + b2[lane]);
    }
    sh2[warp][lane] = a;
    __syncwarp();

    // fc3 (32->2): lane l contributes k=l, warp-reduce
    float hv = sh2[warp][lane];
    float o0 = hv * w3[lane * 2];
    float o1 = hv * w3[lane * 2 + 1];
#pragma unroll
    for (int off = 16; off > 0; off >>= 1) {
        o0 += __shfl_down_sync(0xffffffffu, o0, off);
        o1 += __shfl_down_sync(0xffffffffu, o1, off);
    }
    if (lane == 0) {
        float l0 = o0 + fc3b[0];
        float l1 = o1 + fc3b[1];
        float m = fmaxf(l0, l1);
        float lse = m + logf(expf(l0 - m) + expf(l1 - m));
        out[row * 2]     = l0 - lse;
        out[row * 2 + 1] = l1 - lse;
    }
}

// ---------------- launch -------------------------------------------------------
extern "C" void kernel_launch(void* const* d_in, const int* in_sizes, int n_in,
                              void* d_out, int out_size) {
    (void)in_sizes; (void)n_in; (void)out_size;
    const float* x       = (const float*)d_in[0];
    const int*   esrc    = (const int*)d_in[1];
    const int*   edst    = (const int*)d_in[2];
    const int*   gidx    = (const int*)d_in[3];
    const int*   sidx    = (const int*)d_in[4];
    const float* w_root0 = (const float*)d_in[5];
    const float* w_rel0  = (const float*)d_in[6];
    const float* b0      = (const float*)d_in[7];
    const float* w_rooth = (const float*)d_in[8];
    const float* w_relh  = (const float*)d_in[9];
    const float* b_h     = (const float*)d_in[10];
    const float* fc1w    = (const float*)d_in[11];
    const float* fc1b    = (const float*)d_in[12];
    const float* fc2w    = (const float*)d_in[13];
    const float* fc2b    = (const float*)d_in[14];
    const float* fc3w    = (const float*)d_in[15];
    const float* fc3b    = (const float*)d_in[16];
    float* out = (float*)d_out;

    int* dev_deg;   cudaGetSymbolAddress((void**)&dev_deg, deg_buf);
    int* dev_rs;    cudaGetSymbolAddress((void**)&dev_rs, row_start_buf);
    int* dev_cur;   cudaGetSymbolAddress((void**)&dev_cur, cursor_buf);
    int* dev_csr;   cudaGetSymbolAddress((void**)&dev_csr, csr_src_buf);
    int* dev_sdeg;  cudaGetSymbolAddress((void**)&dev_sdeg, seg_deg_buf);
    int* dev_srs;   cudaGetSymbolAddress((void**)&dev_srs, seg_row_start);
    int* dev_scur;  cudaGetSymbolAddress((void**)&dev_scur, seg_cursor);
    int* dev_sval;  cudaGetSymbolAddress((void**)&dev_sval, seg_val_buf);
    int* dev_bs;    cudaGetSymbolAddress((void**)&dev_bs, blk_sums_buf);
    int* dev_bs2;   cudaGetSymbolAddress((void**)&dev_bs2, blk_sums2_buf);

    // side stream + events (created once; no device allocations)
    static cudaStream_t s2 = nullptr;
    static cudaEvent_t evFork = nullptr, evZero = nullptr, evJoin = nullptr, evJoin2 = nullptr;
    if (s2 == nullptr) {
        cudaStreamCreateWithFlags(&s2, cudaStreamNonBlocking);
        cudaEventCreateWithFlags(&evFork, cudaEventDisableTiming);
        cudaEventCreateWithFlags(&evZero, cudaEventDisableTiming);
        cudaEventCreateWithFlags(&evJoin, cudaEventDisableTiming);
        cudaEventCreateWithFlags(&evJoin2, cudaEventDisableTiming);
    }

    cudaEventRecord(evFork, 0);
    cudaStreamWaitEvent(s2, evFork, 0);

    // main: zero counters + edge CSR
    zero_init<<<(NN + 255) / 256, 256>>>();                           // 0
    cudaEventRecord(evZero, 0);
    degree_count_g<<<EE / 256, 256>>>(edst, dev_deg, EE);             // 1
    scan_deg<<<NB_N, 1024>>>(dev_deg, dev_rs, dev_bs, NN);            // 2

    // s2: layer-0 GEMM (only needs x + weights), then segment CSR
    gemm_dual<<<PGRID, 256, 0, s2>>>(x, w_root0, w_rel0, b0, 0, 1);   // 3 (profiled)
    cudaEventRecord(evJoin, s2);
    cudaStreamWaitEvent(s2, evZero, 0);
    degree_count_g<<<(AA + 255) / 256, 256, 0, s2>>>(sidx, dev_sdeg, AA);
    scan_deg<<<NB_S, 1024, 0, s2>>>(dev_sdeg, dev_srs, dev_bs2, SS);
    scan_fin<<<NB_S, 1024, 0, s2>>>(dev_srs, dev_scur, dev_bs2, SS, AA, NB_S);
    csr_fill_g<<<(AA + 255) / 256, 256, 0, s2>>>(gidx, sidx, dev_scur, dev_sval, AA);
    cudaEventRecord(evJoin2, s2);

    // main: finish edge CSR
    scan_fin<<<NB_N, 1024>>>(dev_rs, dev_cur, dev_bs, NN, EE, NB_N);
    csr_fill_g<<<EE / 256, 256>>>(esrc, edst, dev_cur, dev_csr, EE);

    // join: aggregation needs both edge CSR and gemm0 outputs
    cudaStreamWaitEvent(0, evJoin, 0);
    aggregate<<<NN / 8, 256>>>(1);
    // layer 1: elu(zA) -> zB
    gemm_dual<<<PGRID, 256>>>(x, w_rooth, w_relh, b_h, 1, 2);
    aggregate<<<NN / 8, 256>>>(2);
    // layer 2: elu(zB) -> zA
    gemm_dual<<<PGRID, 256>>>(x, w_rooth + 4096, w_relh + 4096, b_h + 64, 2, 1);
    aggregate<<<NN / 8, 256>>>(1);

    // fused pool + head (needs segment CSR from s2)
    cudaStreamWaitEvent(0, evJoin2, 0);
    mlp_head<<<SS / 8, 256>>>(fc1w, fc1b, fc2w, fc2b, fc3w, fc3b, out);
}

// round 15
// speedup vs baseline: 1.2950x; 1.0263x over previous
#include <cuda_runtime.h>
#include <math.h>

#define NN 100000
#define EE 1600000
#define AA 500000
#define SS 50000
#define FW 64
#define NB_N 98     // ceil(NN/1024)
#define NB_S 49     // ceil(SS/1024)
#define NTILES 3125 // NN/32
#define PGRID 740   // 5 blocks/SM x 148 SMs (exact residency)

typedef unsigned long long u64;

// ---------------- scratch (device globals: no allocations allowed) ------------
__device__ float g_buf[NN * FW];        // h @ w_rel per node
__device__ float zA_buf[NN * FW];       // pre-activation buffers (ping-pong)
__device__ float zB_buf[NN * FW];
__device__ int deg_buf[NN];
__device__ int row_start_buf[NN + 1];
__device__ int cursor_buf[NN];
__device__ int csr_src_buf[EE];
__device__ int seg_deg_buf[SS];
__device__ int seg_row_start[SS + 1];
__device__ int seg_cursor[SS];
__device__ int seg_val_buf[AA];
__device__ int blk_sums_buf[128];
__device__ int blk_sums2_buf[128];      // separate scratch: seg scan runs on s2

__device__ __forceinline__ float elu_f(float x) { return x > 0.f ? x : expm1f(x); }

__device__ __forceinline__ u64 pk2(float lo, float hi) {
    u64 r;
    asm("mov.b64 %0, {%1,%2};" : "=l"(r) : "f"(lo), "f"(hi));
    return r;
}
__device__ __forceinline__ void fma2(u64& d, u64 a, u64 b) {
    asm("fma.rn.f32x2 %0, %1, %2, %0;" : "+l"(d) : "l"(a), "l"(b));
}

// ---------------- init: zero both degree arrays --------------------------------
__global__ void zero_init() {    // grid covers NN
    int i = blockIdx.x * 256 + threadIdx.x;
    if (i < NN) deg_buf[i] = 0;
    if (i < SS) seg_deg_buf[i] = 0;
}

// ---------------- generic CSR build (used for edge CSR and segment CSR) --------
__global__ void degree_count_g(const int* __restrict__ id, int* __restrict__ deg, int n) {
    int e = blockIdx.x * 256 + threadIdx.x;
    if (e < n) atomicAdd(&deg[id[e]], 1);
}

__global__ void scan_deg(const int* __restrict__ deg, int* __restrict__ rowst,
                         int* __restrict__ blks, int n) {
    __shared__ int sm[1024];
    int t = threadIdx.x, b = blockIdx.x;
    int i = b * 1024 + t;
    int v = (i < n) ? deg[i] : 0;
    sm[t] = v;
    __syncthreads();
    for (int off = 1; off < 1024; off <<= 1) {
        int x = (t >= off) ? sm[t - off] : 0;
        __syncthreads();
        sm[t] += x;
        __syncthreads();
    }
    if (i < n) rowst[i] = sm[t] - v;  // block-local exclusive
    if (t == 1023) blks[b] = sm[t];
}

// redundant per-block reduction of preceding block sums, fused with final scatter
__global__ void scan_fin(int* __restrict__ rowst, int* __restrict__ cursor,
                         const int* __restrict__ blks, int n, int total, int nb) {
    __shared__ int sm[128];
    int t = threadIdx.x, b = blockIdx.x;
    if (t < 128) sm[t] = (t < b && t < nb) ? blks[t] : 0;
    __syncthreads();
    for (int o = 64; o > 0; o >>= 1) {
        if (t < o) sm[t] += sm[t + o];
        __syncthreads();
    }
    int off = sm[0];
    int i = b * 1024 + t;
    if (i < n) {
        int rs = rowst[i] + off;
        rowst[i] = rs;
        cursor[i] = rs;
    }
    if (i == 0) rowst[n] = total;
}

__global__ void csr_fill_g(const int* __restrict__ val, const int* __restrict__ dstid,
                           int* __restrict__ cursor, int* __restrict__ out, int n) {
    int e = blockIdx.x * 256 + threadIdx.x;
    if (e < n) {
        int d = dstid[e];
        int p = atomicAdd(&cursor[d], 1);
        out[p] = val[e];
    }
}

// ---------------- fused dual GEMM: z = elu?(h)@wr + b,  g = elu?(h)@wl --------
// PERSISTENT R14 kernel + forced 5-block/SM residency (<=51 regs). Each block
// loads the 32KB combined weight tile ONCE and loops over ~4-5 row-tiles.
// Inner tile: warp owns 4 rows, lane owns 4 cols (lanes 0-15 -> z, 16-31 -> g).
__global__ void __launch_bounds__(256, 5) gemm_dual(
    const float* __restrict__ x_in,
    const float* __restrict__ wr, const float* __restrict__ wl,
    const float* __restrict__ bias,
    int insel, int outsel)
{
    const float* hin = (insel == 0) ? x_in : (insel == 1 ? zA_buf : zB_buf);
    float* z = (outsel == 1) ? zA_buf : zB_buf;
    const bool ap = (insel != 0);

    __shared__ float sw[64 * 128];   // combined [k][c]: c<64 -> wr, c>=64 -> wl
    __shared__ float sh[32 * 64];    // h tile (post-elu)

    int tid = threadIdx.x;
    // weights loaded ONCE per block (amortized over all tiles)
    for (int idx = tid; idx < 64 * 128; idx += 256) {
        int k = idx >> 7, c = idx & 127;
        sw[idx] = (c < 64) ? wr[k * 64 + c] : wl[k * 64 + (c - 64)];
    }

    int warp = tid >> 5, lane = tid & 31;
    int r0 = warp * 4;

    u64 bias0 = 0ull, bias1 = 0ull;
    if (lane < 16) {
        float4 b4 = *(const float4*)(bias + lane * 4);
        bias0 = pk2(b4.x, b4.y);
        bias1 = pk2(b4.z, b4.w);
    }

    const float* swp = sw + (lane << 2);

    for (int tile = blockIdx.x; tile < NTILES; tile += PGRID) {
        int rowBase = tile * 32;
        __syncthreads();                 // prior compute done before sh overwrite
        for (int idx = tid; idx < 32 * 64; idx += 256) {
            float v = hin[(size_t)rowBase * 64 + idx];
            if (ap) v = elu_f(v);
            sh[idx] = v;
        }
        __syncthreads();

        u64 acc[4][2];
#pragma unroll
        for (int r = 0; r < 4; r++) { acc[r][0] = bias0; acc[r][1] = bias1; }

#pragma unroll
        for (int k0 = 0; k0 < 64; k0 += 4) {
            float4 a4[4];
#pragma unroll
            for (int r = 0; r < 4; r++)
                a4[r] = *(const float4*)(sh + (r0 + r) * 64 + k0);
#pragma unroll
            for (int kk = 0; kk < 4; kk++) {
                ulonglong2 wp = *(const ulonglong2*)(swp + ((k0 + kk) << 7));
#pragma unroll
                for (int r = 0; r < 4; r++) {
                    float a = (kk == 0) ? a4[r].x : (kk == 1) ? a4[r].y
                            : (kk == 2) ? a4[r].z : a4[r].w;
                    u64 a2 = pk2(a, a);
                    fma2(acc[r][0], a2, wp.x);
                    fma2(acc[r][1], a2, wp.y);
                }
            }
        }

#pragma unroll
        for (int r = 0; r < 4; r++) {
            int row = rowBase + r0 + r;
            float2 p0 = *(float2*)&acc[r][0];
            float2 p1 = *(float2*)&acc[r][1];
            float4 o = make_float4(p0.x, p0.y, p1.x, p1.y);
            if (lane < 16)
                *(float4*)(z + (size_t)row * 64 + lane * 4) = o;
            else
                *(float4*)(g_buf + (size_t)row * 64 + (lane - 16) * 4) = o;
        }
    }
}

// ---------------- aggregation (EXACT R6): z[i] += sum_{j in in(i)} g[j] --------
// warp per node; 2 lane-halves x float4; 4 edges in flight per half.
__global__ void __launch_bounds__(256) aggregate(int outsel) {
    float* z = (outsel == 1) ? zA_buf : zB_buf;
    int node = (blockIdx.x * 256 + threadIdx.x) >> 5;  // NN/8 = 12500 blocks
    int lane = threadIdx.x & 31;
    int half = lane >> 4, c4 = lane & 15;
    int s = row_start_buf[node], e = row_start_buf[node + 1];
    float4 acc = make_float4(0.f, 0.f, 0.f, 0.f);
    const float* gb = g_buf + c4 * 4;

    int i = s + half;
    for (; i + 6 < e; i += 8) {         // 4 edges per half, 8 per warp
        int i0 = __ldg(&csr_src_buf[i]);
        int i1 = __ldg(&csr_src_buf[i + 2]);
        int i2 = __ldg(&csr_src_buf[i + 4]);
        int i3 = __ldg(&csr_src_buf[i + 6]);
        float4 v0 = *(const float4*)(gb + (size_t)i0 * FW);
        float4 v1 = *(const float4*)(gb + (size_t)i1 * FW);
        float4 v2 = *(const float4*)(gb + (size_t)i2 * FW);
        float4 v3 = *(const float4*)(gb + (size_t)i3 * FW);
        acc.x += (v0.x + v1.x) + (v2.x + v3.x);
        acc.y += (v0.y + v1.y) + (v2.y + v3.y);
        acc.z += (v0.z + v1.z) + (v2.z + v3.z);
        acc.w += (v0.w + v1.w) + (v2.w + v3.w);
    }
    for (; i < e; i += 2) {
        int srcn = __ldg(&csr_src_buf[i]);
        float4 v = *(const float4*)(gb + (size_t)srcn * FW);
        acc.x += v.x; acc.y += v.y; acc.z += v.z; acc.w += v.w;
    }

    acc.x += __shfl_xor_sync(0xffffffffu, acc.x, 16);
    acc.y += __shfl_xor_sync(0xffffffffu, acc.y, 16);
    acc.z += __shfl_xor_sync(0xffffffffu, acc.z, 16);
    acc.w += __shfl_xor_sync(0xffffffffu, acc.w, 16);
    if (lane < 16) {
        float4* zp = (float4*)(z + (size_t)node * FW + c4 * 4);
        float4 o = *zp;
        o.x += acc.x; o.y += acc.y; o.z += acc.z; o.w += acc.w;
        *zp = o;
    }
}

// ---------------- fused pool + MLP head + log_softmax (EXACT R6) ---------------
__global__ void __launch_bounds__(256) mlp_head(
    const float* __restrict__ fc1w, const float* __restrict__ fc1b,
    const float* __restrict__ fc2w, const float* __restrict__ fc2b,
    const float* __restrict__ fc3w, const float* __restrict__ fc3b,
    float* __restrict__ out)
{
    __shared__ u64 w1p[64 * 32];     // [k][l] = {w1[k][l], w1[k][l+32]}
    __shared__ u64 w2p[32 * 32];     // [k2][l] = {w2[2k2][l], w2[2k2+1][l]}
    __shared__ float w3[64];
    __shared__ float b1[64], b2[32];
    __shared__ float sp[8][64];
    __shared__ float sh1[8][64];
    __shared__ float sh2[8][32];

    int tid = threadIdx.x;
    for (int i = tid; i < 2048; i += 256) {
        int k = i >> 5, l = i & 31;
        w1p[i] = pk2(fc1w[k * 64 + l], fc1w[k * 64 + l + 32]);
    }
    for (int i = tid; i < 1024; i += 256) {
        int k2 = i >> 5, l = i & 31;
        w2p[i] = pk2(fc2w[(2 * k2) * 32 + l], fc2w[(2 * k2 + 1) * 32 + l]);
    }
    if (tid < 64) w3[tid] = fc3w[tid];
    if (tid < 64) b1[tid] = fc1b[tid];
    if (tid < 32) b2[tid] = fc2b[tid];
    __syncthreads();

    int warp = tid >> 5, lane = tid & 31;
    int row = blockIdx.x * 8 + warp;   // SS/8 = 6250 blocks exact

    // inline segment pooling: lane owns 2 feature cols
    int s = seg_row_start[row], e = seg_row_start[row + 1];
    float2 acc = make_float2(0.f, 0.f);
    const float* zb = zA_buf + lane * 2;
    int i = s;
    for (; i + 3 < e; i += 4) {
        int n0 = __ldg(&seg_val_buf[i]);
        int n1 = __ldg(&seg_val_buf[i + 1]);
        int n2 = __ldg(&seg_val_buf[i + 2]);
        int n3 = __ldg(&seg_val_buf[i + 3]);
        float2 v0 = *(const float2*)(zb + (size_t)n0 * FW);
        float2 v1 = *(const float2*)(zb + (size_t)n1 * FW);
        float2 v2 = *(const float2*)(zb + (size_t)n2 * FW);
        float2 v3 = *(const float2*)(zb + (size_t)n3 * FW);
        acc.x += elu_f(v0.x) + elu_f(v1.x) + elu_f(v2.x) + elu_f(v3.x);
        acc.y += elu_f(v0.y) + elu_f(v1.y) + elu_f(v2.y) + elu_f(v3.y);
    }
    for (; i < e; i++) {
        int n0 = __ldg(&seg_val_buf[i]);
        float2 v0 = *(const float2*)(zb + (size_t)n0 * FW);
        acc.x += elu_f(v0.x);
        acc.y += elu_f(v0.y);
    }
    sp[warp][lane * 2] = acc.x;
    sp[warp][lane * 2 + 1] = acc.y;
    __syncwarp();

    // fc1 (64->64) + elu : packed over the two output halves
    u64 acc12 = pk2(b1[lane], b1[lane + 32]);
#pragma unroll
    for (int k = 0; k < 64; k++) {
        float pk = sp[warp][k];
        fma2(acc12, pk2(pk, pk), w1p[k * 32 + lane]);
    }
    {
        float2 a12 = *(float2*)&acc12;
        sh1[warp][lane] = elu_f(a12.x);
        sh1[warp][lane + 32] = elu_f(a12.y);
    }
    __syncwarp();

    // fc2 (64->32) + elu : packed over even/odd k
    u64 acc2 = 0ull;
#pragma unroll
    for (int k2 = 0; k2 < 32; k2++) {
        u64 hpair = *(const u64*)(&sh1[warp][2 * k2]);
        fma2(acc2, hpair, w2p[k2 * 32 + lane]);
    }
    float a;
    {
        float2 a2f = *(float2*)&acc2;
        a = elu_f(a2f.x + a2f.y + b2[lane]);
    }
    sh2[warp][lane] = a;
    __syncwarp();

    // fc3 (32->2): lane l contributes k=l, warp-reduce
    float hv = sh2[warp][lane];
    float o0 = hv * w3[lane * 2];
    float o1 = hv * w3[lane * 2 + 1];
#pragma unroll
    for (int off = 16; off > 0; off >>= 1) {
        o0 += __shfl_down_sync(0xffffffffu, o0, off);
        o1 += __shfl_down_sync(0xffffffffu, o1, off);
    }
    if (lane == 0) {
        float l0 = o0 + fc3b[0];
        float l1 = o1 + fc3b[1];
        float m = fmaxf(l0, l1);
        float lse = m + logf(expf(l0 - m) + expf(l1 - m));
        out[row * 2]     = l0 - lse;
        out[row * 2 + 1] = l1 - lse;
    }
}

// ---------------- launch -------------------------------------------------------
extern "C" void kernel_launch(void* const* d_in, const int* in_sizes, int n_in,
                              void* d_out, int out_size) {
    (void)in_sizes; (void)n_in; (void)out_size;
    const float* x       = (const float*)d_in[0];
    const int*   esrc    = (const int*)d_in[1];
    const int*   edst    = (const int*)d_in[2];
    const int*   gidx    = (const int*)d_in[3];
    const int*   sidx    = (const int*)d_in[4];
    const float* w_root0 = (const float*)d_in[5];
    const float* w_rel0  = (const float*)d_in[6];
    const float* b0      = (const float*)d_in[7];
    const float* w_rooth = (const float*)d_in[8];
    const float* w_relh  = (const float*)d_in[9];
    const float* b_h     = (const float*)d_in[10];
    const float* fc1w    = (const float*)d_in[11];
    const float* fc1b    = (const float*)d_in[12];
    const float* fc2w    = (const float*)d_in[13];
    const float* fc2b    = (const float*)d_in[14];
    const float* fc3w    = (const float*)d_in[15];
    const float* fc3b    = (const float*)d_in[16];
    float* out = (float*)d_out;

    int* dev_deg;   cudaGetSymbolAddress((void**)&dev_deg, deg_buf);
    int* dev_rs;    cudaGetSymbolAddress((void**)&dev_rs, row_start_buf);
    int* dev_cur;   cudaGetSymbolAddress((void**)&dev_cur, cursor_buf);
    int* dev_csr;   cudaGetSymbolAddress((void**)&dev_csr, csr_src_buf);
    int* dev_sdeg;  cudaGetSymbolAddress((void**)&dev_sdeg, seg_deg_buf);
    int* dev_srs;   cudaGetSymbolAddress((void**)&dev_srs, seg_row_start);
    int* dev_scur;  cudaGetSymbolAddress((void**)&dev_scur, seg_cursor);
    int* dev_sval;  cudaGetSymbolAddress((void**)&dev_sval, seg_val_buf);
    int* dev_bs;    cudaGetSymbolAddress((void**)&dev_bs, blk_sums_buf);
    int* dev_bs2;   cudaGetSymbolAddress((void**)&dev_bs2, blk_sums2_buf);

    // side stream + events (created once; no device allocations)
    static cudaStream_t s2 = nullptr;
    static cudaEvent_t evFork = nullptr, evZero = nullptr, evJoin = nullptr, evJoin2 = nullptr;
    if (s2 == nullptr) {
        cudaStreamCreateWithFlags(&s2, cudaStreamNonBlocking);
        cudaEventCreateWithFlags(&evFork, cudaEventDisableTiming);
        cudaEventCreateWithFlags(&evZero, cudaEventDisableTiming);
        cudaEventCreateWithFlags(&evJoin, cudaEventDisableTiming);
        cudaEventCreateWithFlags(&evJoin2, cudaEventDisableTiming);
    }

    cudaEventRecord(evFork, 0);
    cudaStreamWaitEvent(s2, evFork, 0);

    // main: zero counters + edge CSR
    zero_init<<<(NN + 255) / 256, 256>>>();                           // 0
    cudaEventRecord(evZero, 0);
    degree_count_g<<<EE / 256, 256>>>(edst, dev_deg, EE);             // 1
    scan_deg<<<NB_N, 1024>>>(dev_deg, dev_rs, dev_bs, NN);            // 2

    // s2: layer-0 GEMM (only needs x + weights), then segment CSR
    gemm_dual<<<PGRID, 256, 0, s2>>>(x, w_root0, w_rel0, b0, 0, 1);   // 3 (profiled)
    cudaEventRecord(evJoin, s2);
    cudaStreamWaitEvent(s2, evZero, 0);
    degree_count_g<<<(AA + 255) / 256, 256, 0, s2>>>(sidx, dev_sdeg, AA);
    scan_deg<<<NB_S, 1024, 0, s2>>>(dev_sdeg, dev_srs, dev_bs2, SS);
    scan_fin<<<NB_S, 1024, 0, s2>>>(dev_srs, dev_scur, dev_bs2, SS, AA, NB_S);
    csr_fill_g<<<(AA + 255) / 256, 256, 0, s2>>>(gidx, sidx, dev_scur, dev_sval, AA);
    cudaEventRecord(evJoin2, s2);

    // main: finish edge CSR
    scan_fin<<<NB_N, 1024>>>(dev_rs, dev_cur, dev_bs, NN, EE, NB_N);
    csr_fill_g<<<EE / 256, 256>>>(esrc, edst, dev_cur, dev_csr, EE);

    // join: aggregation needs both edge CSR and gemm0 outputs
    cudaStreamWaitEvent(0, evJoin, 0);
    aggregate<<<NN / 8, 256>>>(1);
    // layer 1: elu(zA) -> zB
    gemm_dual<<<PGRID, 256>>>(x, w_rooth, w_relh, b_h, 1, 2);
    aggregate<<<NN / 8, 256>>>(2);
    // layer 2: elu(zB) -> zA
    gemm_dual<<<PGRID, 256>>>(x, w_rooth + 4096, w_relh + 4096, b_h + 64, 2, 1);
    aggregate<<<NN / 8, 256>>>(1);

    // fused pool + head (needs segment CSR from s2)
    cudaStreamWaitEvent(0, evJoin2, 0);
    mlp_head<<<SS / 8, 256>>>(fc1w, fc1b, fc2w, fc2b, fc3w, fc3b, out);
}